// round 1
// baseline (speedup 1.0000x reference)
#include <cuda_runtime.h>
#include <math.h>

#define NN 50000
#define EE 400000
#define RR 500
#define XS 100
#define GS 100

static __device__ __constant__ float kNEG = 0.01f;
static __device__ __constant__ float kEPS = 1e-12f;

// ------------------------- scratch (device globals) -------------------------
__device__ float d_xn[NN * XS];
__device__ float d_uA[NN * 128];
__device__ float d_vA[NN * 128];
__device__ float d_uB[NN * 128];
__device__ float d_vB[NN * 128];
__device__ float d_accA[NN * 128];
__device__ float d_accB[NN * 128];
__device__ float d_h[NN * 128];
__device__ float d_ent[NN * 64];
__device__ float d_wA[RR * 128];
__device__ float d_wB[RR * 128];
__device__ float d_auA[NN * 2];
__device__ float d_avA[NN * 2];
__device__ float d_auB[NN * 2];
__device__ float d_avB[NN * 2];
__device__ float d_awA[RR * 2];
__device__ float d_awB[RR * 2];
__device__ float d_ebuf[EE * 2];
__device__ float d_denom[NN * 2];

// ------------------------- helpers -------------------------
__device__ __forceinline__ float wsum(float v) {
#pragma unroll
    for (int o = 16; o > 0; o >>= 1) v += __shfl_xor_sync(0xffffffffu, v, o);
    return v;
}

__global__ void zero_f(float* __restrict__ p, int n) {
    int i = blockIdx.x * blockDim.x + threadIdx.x;
    if (i < n) p[i] = 0.f;
}

// L2-normalize rows of x [NN, XS]; blockDim = 128, one block per row
__global__ void norm_x(const float* __restrict__ x, float* __restrict__ xn) {
    int i = blockIdx.x;
    int j = threadIdx.x;
    float v = (j < XS) ? x[i * XS + j] : 0.f;
    float s = wsum(v * v);
    __shared__ float sm[4];
    if ((j & 31) == 0) sm[j >> 5] = s;
    __syncthreads();
    float tot = sm[0] + sm[1] + sm[2] + sm[3];
    if (j < XS) xn[i * XS + j] = v / fmaxf(sqrtf(tot), kEPS);
}

// C[M x (64*gridDim.y)] = A[M x K] @ W[:, koff:koff+K].T (+bias)
// W row-major [nOutTotal, ldw]; C row stride = ldc
__global__ __launch_bounds__(256) void gemm_wt(
    const float* __restrict__ A, int lda,
    const float* __restrict__ W, int ldw, int koff, int K,
    const float* __restrict__ bias,
    float* __restrict__ C, int ldc, int M)
{
    __shared__ float As[64][17];
    __shared__ float Bs[16][65];
    int m0 = blockIdx.x * 64, n0 = blockIdx.y * 64;
    int tx = threadIdx.x & 15, ty = threadIdx.x >> 4;
    float acc[4][4] = {};
    for (int k0 = 0; k0 < K; k0 += 16) {
#pragma unroll
        for (int i = 0; i < 4; i++) {
            int li = threadIdx.x + i * 256;
            int k = li & 15, m = li >> 4;
            int gm = m0 + m, gk = k0 + k;
            As[m][k] = (gm < M && gk < K) ? A[gm * lda + gk] : 0.f;
        }
#pragma unroll
        for (int i = 0; i < 4; i++) {
            int li = threadIdx.x + i * 256;
            int k = li & 15, n = li >> 4;
            int gk = k0 + k;
            Bs[k][n] = (gk < K) ? W[(n0 + n) * ldw + koff + gk] : 0.f;
        }
        __syncthreads();
#pragma unroll
        for (int k = 0; k < 16; k++) {
            float a[4], b[4];
#pragma unroll
            for (int i = 0; i < 4; i++) a[i] = As[ty * 4 + i][k];
#pragma unroll
            for (int j = 0; j < 4; j++) b[j] = Bs[k][tx * 4 + j];
#pragma unroll
            for (int i = 0; i < 4; i++)
#pragma unroll
                for (int j = 0; j < 4; j++)
                    acc[i][j] = fmaf(a[i], b[j], acc[i][j]);
        }
        __syncthreads();
    }
#pragma unroll
    for (int i = 0; i < 4; i++) {
        int gm = m0 + ty * 4 + i;
        if (gm >= M) continue;
#pragma unroll
        for (int j = 0; j < 4; j++) {
            int gn = n0 + tx * 4 + j;
            float v = acc[i][j];
            if (bias) v += bias[gn];
            C[gm * ldc + gn] = v;
        }
    }
}

// out[r, n] = bias[n] + sum_k W[n, koff+k] * gmat[r, k]   (small R)
__global__ void relproj(const float* __restrict__ gmat, int Kg,
                        const float* __restrict__ W, int ldw, int koff,
                        const float* __restrict__ bias,
                        float* __restrict__ out, int Rn, int ncols)
{
    int idx = blockIdx.x * blockDim.x + threadIdx.x;
    if (idx >= Rn * ncols) return;
    int r = idx / ncols, n = idx - r * ncols;
    float acc = bias ? bias[n] : 0.f;
    for (int k = 0; k < Kg; k++)
        acc = fmaf(W[n * ldw + koff + k], gmat[r * Kg + k], acc);
    out[idx] = acc;
}

// out[m, h] = sum_k att[h*64+k] * mat[m, h*64+k]; warp per row, blockDim 256
__global__ void attdot(const float* __restrict__ mat, const float* __restrict__ att,
                       float* __restrict__ out, int M)
{
    int row = blockIdx.x * 8 + (threadIdx.x >> 5);
    if (row >= M) return;
    int l = threadIdx.x & 31;
    float s = 0.f;
#pragma unroll
    for (int i = 0; i < 4; i++) {
        int c = l * 4 + i;
        s = fmaf(mat[row * 128 + c], att[c], s);
    }
#pragma unroll
    for (int o = 8; o > 0; o >>= 1) s += __shfl_xor_sync(0xffffffffu, s, o);
    if (l == 0) out[row * 2 + 0] = s;
    if (l == 16) out[row * 2 + 1] = s;
}

// per edge: e = exp(leaky(au[seg] + av[oth] + aw[t])), denom[seg] += e
__global__ void pass_a(const int* __restrict__ seg, const int* __restrict__ oth,
                       const int* __restrict__ et,
                       const float* __restrict__ au, const float* __restrict__ av,
                       const float* __restrict__ aw,
                       float* __restrict__ ebuf, float* __restrict__ denom)
{
    int e = blockIdx.x * blockDim.x + threadIdx.x;
    if (e >= EE) return;
    int s = seg[e], o = oth[e], t = et[e];
#pragma unroll
    for (int h = 0; h < 2; h++) {
        float a = au[s * 2 + h] + av[o * 2 + h] + aw[t * 2 + h];
        a = (a > 0.f) ? a : kNEG * a;
        float ex = expf(a);
        ebuf[e * 2 + h] = ex;
        atomicAdd(&denom[s * 2 + h], ex);
    }
}

// per (edge, j<128): out[oth, j] += (e/denom[seg]) * (u[seg,j] + v[oth,j] + w[t,j])
__global__ void pass_b(const int* __restrict__ seg, const int* __restrict__ oth,
                       const int* __restrict__ et,
                       const float* __restrict__ u, const float* __restrict__ v,
                       const float* __restrict__ w,
                       const float* __restrict__ ebuf, const float* __restrict__ denom,
                       float* __restrict__ out)
{
    int idx = blockIdx.x * blockDim.x + threadIdx.x;
    if (idx >= EE * 128) return;
    int e = idx >> 7, j = idx & 127;
    int s = seg[e], o = oth[e], t = et[e];
    int h = j >> 6;
    float alpha = ebuf[e * 2 + h] / denom[s * 2 + h];
    float c = u[s * 128 + j] + v[o * 128 + j] + w[t * 128 + j];
    atomicAdd(&out[o * 128 + j], alpha * c);
}

// out = l2norm_per_head(leaky(0.5*a + 0.5*b)); block=128 per node
__global__ void combine(const float* __restrict__ a, const float* __restrict__ b,
                        float* __restrict__ out)
{
    int i = blockIdx.x, j = threadIdx.x;
    float v = 0.5f * a[i * 128 + j] + 0.5f * b[i * 128 + j];
    v = (v > 0.f) ? v : kNEG * v;
    float s = wsum(v * v);
    __shared__ float sm[4];
    if ((j & 31) == 0) sm[j >> 5] = s;
    __syncthreads();
    int h = j >> 6;
    float tot = sm[h * 2] + sm[h * 2 + 1];
    out[i * 128 + j] = v / fmaxf(sqrtf(tot), kEPS);
}

// h_prime = l2norm_128(ent broadcast over heads + h); block=128 per node
__global__ void final_k(const float* __restrict__ ent, const float* __restrict__ h,
                        float* __restrict__ out)
{
    int i = blockIdx.x, j = threadIdx.x;
    float v = ent[i * 64 + (j & 63)] + h[i * 128 + j];
    float s = wsum(v * v);
    __shared__ float sm[4];
    if ((j & 31) == 0) sm[j >> 5] = s;
    __syncthreads();
    float tot = sm[0] + sm[1] + sm[2] + sm[3];
    out[i * 128 + j] = v / fmaxf(sqrtf(tot), kEPS);
}

// ------------------------- host orchestration -------------------------
namespace {
struct Ptrs {
    float *xn, *uA, *vA, *uB, *vB, *accA, *accB, *h, *ent, *wA, *wB;
    float *auA, *avA, *auB, *avB, *awA, *awB, *ebuf, *denom;
};

static void get_ptrs(Ptrs& p) {
    cudaGetSymbolAddress((void**)&p.xn, d_xn);
    cudaGetSymbolAddress((void**)&p.uA, d_uA);
    cudaGetSymbolAddress((void**)&p.vA, d_vA);
    cudaGetSymbolAddress((void**)&p.uB, d_uB);
    cudaGetSymbolAddress((void**)&p.vB, d_vB);
    cudaGetSymbolAddress((void**)&p.accA, d_accA);
    cudaGetSymbolAddress((void**)&p.accB, d_accB);
    cudaGetSymbolAddress((void**)&p.h, d_h);
    cudaGetSymbolAddress((void**)&p.ent, d_ent);
    cudaGetSymbolAddress((void**)&p.wA, d_wA);
    cudaGetSymbolAddress((void**)&p.wB, d_wB);
    cudaGetSymbolAddress((void**)&p.auA, d_auA);
    cudaGetSymbolAddress((void**)&p.avA, d_avA);
    cudaGetSymbolAddress((void**)&p.auB, d_auB);
    cudaGetSymbolAddress((void**)&p.avB, d_avB);
    cudaGetSymbolAddress((void**)&p.awA, d_awA);
    cudaGetSymbolAddress((void**)&p.awB, d_awB);
    cudaGetSymbolAddress((void**)&p.ebuf, d_ebuf);
    cudaGetSymbolAddress((void**)&p.denom, d_denom);
}

// One attention layer (both directions + combine): A [NN x K] input features.
static void run_layer(const Ptrs& p,
                      const float* A, int lda, int K, int ldw,
                      const float* Wi, const float* bi, const float* ai,
                      const float* Wo, const float* bo, const float* ao,
                      const float* g,
                      const int* rowp, const int* colp, const int* et,
                      float* outH)
{
    dim3 gg((NN + 63) / 64, 2);
    // node projections: u = A @ W[:, :K].T ; v = A @ W[:, K:2K].T
    gemm_wt<<<gg, 256>>>(A, lda, Wi, ldw, 0, K, nullptr, p.uA, 128, NN);
    gemm_wt<<<gg, 256>>>(A, lda, Wi, ldw, K, K, nullptr, p.vA, 128, NN);
    gemm_wt<<<gg, 256>>>(A, lda, Wo, ldw, 0, K, nullptr, p.uB, 128, NN);
    gemm_wt<<<gg, 256>>>(A, lda, Wo, ldw, K, K, nullptr, p.vB, 128, NN);
    // relation projections (bias folded here)
    relproj<<<(RR * 128 + 255) / 256, 256>>>(g, GS, Wi, ldw, 2 * K, bi, p.wA, RR, 128);
    relproj<<<(RR * 128 + 255) / 256, 256>>>(g, GS, Wo, ldw, 2 * K, bo, p.wB, RR, 128);
    // attention scalar precomputes
    attdot<<<(NN + 7) / 8, 256>>>(p.uA, ai, p.auA, NN);
    attdot<<<(NN + 7) / 8, 256>>>(p.vA, ai, p.avA, NN);
    attdot<<<(NN + 7) / 8, 256>>>(p.uB, ao, p.auB, NN);
    attdot<<<(NN + 7) / 8, 256>>>(p.vB, ao, p.avB, NN);
    attdot<<<(RR + 7) / 8, 256>>>(p.wA, ai, p.awA, RR);
    attdot<<<(RR + 7) / 8, 256>>>(p.wB, ao, p.awB, RR);
    // accumulators
    zero_f<<<(NN * 128 + 255) / 256, 256>>>(p.accA, NN * 128);
    zero_f<<<(NN * 128 + 255) / 256, 256>>>(p.accB, NN * 128);
    // "in" direction: seg=row, scatter to col
    zero_f<<<(NN * 2 + 255) / 256, 256>>>(p.denom, NN * 2);
    pass_a<<<(EE + 255) / 256, 256>>>(rowp, colp, et, p.auA, p.avA, p.awA, p.ebuf, p.denom);
    pass_b<<<(EE * 128 + 255) / 256, 256>>>(rowp, colp, et, p.uA, p.vA, p.wA,
                                            p.ebuf, p.denom, p.accA);
    // "out" direction: seg=col, scatter to row
    zero_f<<<(NN * 2 + 255) / 256, 256>>>(p.denom, NN * 2);
    pass_a<<<(EE + 255) / 256, 256>>>(colp, rowp, et, p.auB, p.avB, p.awB, p.ebuf, p.denom);
    pass_b<<<(EE * 128 + 255) / 256, 256>>>(colp, rowp, et, p.uB, p.vB, p.wB,
                                            p.ebuf, p.denom, p.accB);
    combine<<<NN, 128>>>(p.accA, p.accB, outH);
}
}  // namespace

extern "C" void kernel_launch(void* const* d_in, const int* in_sizes, int n_in,
                              void* d_out, int out_size)
{
    const float* x   = (const float*)d_in[0];
    const float* g   = (const float*)d_in[1];
    const int*   ei  = (const int*)d_in[2];
    const int*   et  = (const int*)d_in[3];
    const float* W1i = (const float*)d_in[4];
    const float* b1i = (const float*)d_in[5];
    const float* a1i = (const float*)d_in[6];
    const float* W1o = (const float*)d_in[7];
    const float* b1o = (const float*)d_in[8];
    const float* a1o = (const float*)d_in[9];
    const float* W2i = (const float*)d_in[10];
    const float* b2i = (const float*)d_in[11];
    const float* a2i = (const float*)d_in[12];
    const float* W2o = (const float*)d_in[13];
    const float* b2o = (const float*)d_in[14];
    const float* a2o = (const float*)d_in[15];
    const float* We  = (const float*)d_in[16];
    const float* be  = (const float*)d_in[17];
    const float* Wr  = (const float*)d_in[18];
    const float* br  = (const float*)d_in[19];
    float* out = (float*)d_out;

    const int* rowp = ei;
    const int* colp = ei + EE;

    Ptrs p;
    get_ptrs(p);

    // x normalize
    norm_x<<<NN, 128>>>(x, p.xn);

    // layer 1: input xn [NN,100], d1 = 300
    run_layer(p, p.xn, XS, XS, 2 * XS + GS,
              W1i, b1i, a1i, W1o, b1o, a1o, g, rowp, colp, et, p.h);

    // layer 2: input h [NN,128], d2 = 356
    run_layer(p, p.h, 128, 128, 2 * 128 + GS,
              W2i, b2i, a2i, W2o, b2o, a2o, g, rowp, colp, et, p.h);

    // entity layer: ent = xn @ We.T + be  [NN,64]
    dim3 ge((NN + 63) / 64, 1);
    gemm_wt<<<ge, 256>>>(p.xn, XS, We, XS, 0, XS, be, p.ent, 64, NN);

    // h_prime (l2norm over 128) -> out[0 : NN*128)
    final_k<<<NN, 128>>>(p.ent, p.h, out);

    // g_prime = g @ Wr.T + br -> out[NN*128 : NN*128 + RR*128)
    relproj<<<(RR * 128 + 255) / 256, 256>>>(g, GS, Wr, GS, 0, br, out + NN * 128, RR, 128);
}

// round 2
// speedup vs baseline: 1.7505x; 1.7505x over previous
#include <cuda_runtime.h>
#include <math.h>

#define NN 50000
#define EE 400000
#define RR 500
#define XS 100
#define GS 100

static __device__ __constant__ float kNEG = 0.01f;
static __device__ __constant__ float kEPS = 1e-12f;

// ------------------------- scratch (device globals) -------------------------
__device__ float d_xn[NN * XS];
__device__ float d_uA[NN * 128];
__device__ float d_vA[NN * 128];
__device__ float d_uB[NN * 128];
__device__ float d_vB[NN * 128];
__device__ float d_accA[NN * 128];
__device__ float d_accB[NN * 128];
__device__ float d_salA[NN * 2];
__device__ float d_salB[NN * 2];
__device__ float d_h[NN * 128];
__device__ float d_ent[NN * 64];
__device__ float d_wA[RR * 128];
__device__ float d_wB[RR * 128];
__device__ float d_auA[NN * 2];
__device__ float d_avA[NN * 2];
__device__ float d_auB[NN * 2];
__device__ float d_avB[NN * 2];
__device__ float d_awA[RR * 2];
__device__ float d_awB[RR * 2];
__device__ float d_ebuf[EE * 2];
__device__ float d_denom[NN * 2];

// ------------------------- helpers -------------------------
__device__ __forceinline__ float wsum(float v) {
#pragma unroll
    for (int o = 16; o > 0; o >>= 1) v += __shfl_xor_sync(0xffffffffu, v, o);
    return v;
}

__global__ void zero_f(float* __restrict__ p, int n) {
    int i = blockIdx.x * blockDim.x + threadIdx.x;
    if (i < n) p[i] = 0.f;
}

// L2-normalize rows of x [NN, XS]; blockDim = 128, one block per row
__global__ void norm_x(const float* __restrict__ x, float* __restrict__ xn) {
    int i = blockIdx.x;
    int j = threadIdx.x;
    float v = (j < XS) ? x[i * XS + j] : 0.f;
    float s = wsum(v * v);
    __shared__ float sm[4];
    if ((j & 31) == 0) sm[j >> 5] = s;
    __syncthreads();
    float tot = sm[0] + sm[1] + sm[2] + sm[3];
    if (j < XS) xn[i * XS + j] = v / fmaxf(sqrtf(tot), kEPS);
}

// Fused 4-projection GEMM: for y=0..3 computes C_y[M x 128] = A @ Wsel[:, koff:koff+K].T
// y0: (Wi, 0)->uA   y1: (Wi, K)->vA   y2: (Wo, 0)->uB   y3: (Wo, K)->vB
// 128x128 block tile, 256 threads, 8x8 micro-tile.
__global__ __launch_bounds__(256) void gemm4(
    const float* __restrict__ A, int lda, int K,
    const float* __restrict__ Wi, const float* __restrict__ Wo, int ldw,
    float* __restrict__ uA, float* __restrict__ vA,
    float* __restrict__ uB, float* __restrict__ vB, int M)
{
    int y = blockIdx.y;
    const float* W = (y < 2) ? Wi : Wo;
    int koff = (y & 1) ? K : 0;
    float* C = (y == 0) ? uA : (y == 1) ? vA : (y == 2) ? uB : vB;

    __shared__ float As[16][132];   // [k][m]
    __shared__ float Bs[16][132];   // [k][n]
    int m0 = blockIdx.x * 128;
    int tx = threadIdx.x & 15;      // n: tx*8
    int ty = threadIdx.x >> 4;      // m: ty*8
    float acc[8][8] = {};

    for (int k0 = 0; k0 < K; k0 += 16) {
        // A tile: 128x16. Each thread loads 8 consecutive k from one row.
        {
            int m = threadIdx.x >> 1;
            int kb = (threadIdx.x & 1) * 8;
            int gm = m0 + m;
#pragma unroll
            for (int i = 0; i < 8; i++) {
                int gk = k0 + kb + i;
                As[kb + i][m] = (gm < M && gk < K) ? A[gm * lda + gk] : 0.f;
            }
        }
        // B tile: 16x128 from W rows (n-major).
        {
            int n = threadIdx.x >> 1;
            int kb = (threadIdx.x & 1) * 8;
#pragma unroll
            for (int i = 0; i < 8; i++) {
                int gk = k0 + kb + i;
                Bs[kb + i][n] = (gk < K) ? W[n * ldw + koff + gk] : 0.f;
            }
        }
        __syncthreads();
#pragma unroll
        for (int k = 0; k < 16; k++) {
            float4 a0 = *(const float4*)&As[k][ty * 8];
            float4 a1 = *(const float4*)&As[k][ty * 8 + 4];
            float4 b0 = *(const float4*)&Bs[k][tx * 8];
            float4 b1 = *(const float4*)&Bs[k][tx * 8 + 4];
            float av[8] = {a0.x, a0.y, a0.z, a0.w, a1.x, a1.y, a1.z, a1.w};
            float bv[8] = {b0.x, b0.y, b0.z, b0.w, b1.x, b1.y, b1.z, b1.w};
#pragma unroll
            for (int i = 0; i < 8; i++)
#pragma unroll
                for (int j = 0; j < 8; j++)
                    acc[i][j] = fmaf(av[i], bv[j], acc[i][j]);
        }
        __syncthreads();
    }
#pragma unroll
    for (int i = 0; i < 8; i++) {
        int gm = m0 + ty * 8 + i;
        if (gm >= M) continue;
#pragma unroll
        for (int j = 0; j < 8; j += 4) {
            float4 v = make_float4(acc[i][j], acc[i][j + 1], acc[i][j + 2], acc[i][j + 3]);
            *(float4*)&C[gm * 128 + tx * 8 + j] = v;
        }
    }
}

// C[M x N] = A[M x K] @ W.T (+bias) — small-N path (entity layer)
__global__ __launch_bounds__(256) void gemm_wt(
    const float* __restrict__ A, int lda,
    const float* __restrict__ W, int ldw, int K,
    const float* __restrict__ bias,
    float* __restrict__ C, int ldc, int M)
{
    __shared__ float As[64][17];
    __shared__ float Bs[16][65];
    int m0 = blockIdx.x * 64, n0 = blockIdx.y * 64;
    int tx = threadIdx.x & 15, ty = threadIdx.x >> 4;
    float acc[4][4] = {};
    for (int k0 = 0; k0 < K; k0 += 16) {
#pragma unroll
        for (int i = 0; i < 4; i++) {
            int li = threadIdx.x + i * 256;
            int k = li & 15, m = li >> 4;
            int gm = m0 + m, gk = k0 + k;
            As[m][k] = (gm < M && gk < K) ? A[gm * lda + gk] : 0.f;
        }
#pragma unroll
        for (int i = 0; i < 4; i++) {
            int li = threadIdx.x + i * 256;
            int k = li & 15, n = li >> 4;
            int gk = k0 + k;
            Bs[k][n] = (gk < K) ? W[(n0 + n) * ldw + gk] : 0.f;
        }
        __syncthreads();
#pragma unroll
        for (int k = 0; k < 16; k++) {
            float a[4], b[4];
#pragma unroll
            for (int i = 0; i < 4; i++) a[i] = As[ty * 4 + i][k];
#pragma unroll
            for (int j = 0; j < 4; j++) b[j] = Bs[k][tx * 4 + j];
#pragma unroll
            for (int i = 0; i < 4; i++)
#pragma unroll
                for (int j = 0; j < 4; j++)
                    acc[i][j] = fmaf(a[i], b[j], acc[i][j]);
        }
        __syncthreads();
    }
#pragma unroll
    for (int i = 0; i < 4; i++) {
        int gm = m0 + ty * 4 + i;
        if (gm >= M) continue;
#pragma unroll
        for (int j = 0; j < 4; j++) {
            int gn = n0 + tx * 4 + j;
            float v = acc[i][j] + bias[gn];
            C[gm * ldc + gn] = v;
        }
    }
}

// out[r, n] = bias[n] + sum_k W[n, koff+k] * gmat[r, k]   (small R)
__global__ void relproj(const float* __restrict__ gmat, int Kg,
                        const float* __restrict__ W, int ldw, int koff,
                        const float* __restrict__ bias,
                        float* __restrict__ out, int Rn, int ncols)
{
    int idx = blockIdx.x * blockDim.x + threadIdx.x;
    if (idx >= Rn * ncols) return;
    int r = idx / ncols, n = idx - r * ncols;
    float acc = bias ? bias[n] : 0.f;
    for (int k = 0; k < Kg; k++)
        acc = fmaf(W[n * ldw + koff + k], gmat[r * Kg + k], acc);
    out[idx] = acc;
}

// out[m, h] = sum_k att[h*64+k] * mat[m, h*64+k]; warp per row
__global__ void attdot(const float* __restrict__ mat, const float* __restrict__ att,
                       float* __restrict__ out, int M)
{
    int row = blockIdx.x * 8 + (threadIdx.x >> 5);
    if (row >= M) return;
    int l = threadIdx.x & 31;
    float s = 0.f;
#pragma unroll
    for (int i = 0; i < 4; i++) {
        int c = l * 4 + i;
        s = fmaf(mat[row * 128 + c], att[c], s);
    }
#pragma unroll
    for (int o = 8; o > 0; o >>= 1) s += __shfl_xor_sync(0xffffffffu, s, o);
    if (l == 0) out[row * 2 + 0] = s;
    if (l == 16) out[row * 2 + 1] = s;
}

// per edge: e = exp(leaky(au[seg] + av[oth] + aw[t])), denom[seg] += e
__global__ void pass_a(const int* __restrict__ seg, const int* __restrict__ oth,
                       const int* __restrict__ et,
                       const float* __restrict__ au, const float* __restrict__ av,
                       const float* __restrict__ aw,
                       float* __restrict__ ebuf, float* __restrict__ denom)
{
    int e = blockIdx.x * blockDim.x + threadIdx.x;
    if (e >= EE) return;
    int s = seg[e], o = oth[e], t = et[e];
#pragma unroll
    for (int h = 0; h < 2; h++) {
        float a = au[s * 2 + h] + av[o * 2 + h] + aw[t * 2 + h];
        a = (a > 0.f) ? a : kNEG * a;
        float ex = expf(a);
        ebuf[e * 2 + h] = ex;
        atomicAdd(&denom[s * 2 + h], ex);
    }
}

// warp per edge: acc[oth] += alpha*(u[seg] + w[t]) (float4 + vector red),
//                sal[oth,h] += alpha (scalar; the v[oth] term applied later).
__global__ __launch_bounds__(256) void pass_b(
    const int* __restrict__ seg, const int* __restrict__ oth,
    const int* __restrict__ et,
    const float* __restrict__ u, const float* __restrict__ w,
    const float* __restrict__ ebuf, const float* __restrict__ denom,
    float* __restrict__ acc, float* __restrict__ sal)
{
    int e = blockIdx.x * 8 + (threadIdx.x >> 5);
    if (e >= EE) return;
    int l = threadIdx.x & 31;
    int s = seg[e], o = oth[e], t = et[e];
    int h = l >> 4;   // lanes 0-15: channels 0..63 (head 0); lanes 16-31: head 1
    float alpha = ebuf[e * 2 + h] / denom[s * 2 + h];

    const float4* up = (const float4*)(u + (size_t)s * 128);
    const float4* wp = (const float4*)(w + (size_t)t * 128);
    float4 uv = up[l];
    float4 wv = wp[l];
    float4 r;
    r.x = alpha * (uv.x + wv.x);
    r.y = alpha * (uv.y + wv.y);
    r.z = alpha * (uv.z + wv.z);
    r.w = alpha * (uv.w + wv.w);
    float* dst = acc + (size_t)o * 128 + l * 4;
#if __CUDA_ARCH__ >= 900
    asm volatile("red.global.add.v4.f32 [%0], {%1, %2, %3, %4};"
                 :: "l"(dst), "f"(r.x), "f"(r.y), "f"(r.z), "f"(r.w) : "memory");
#else
    atomicAdd(dst + 0, r.x);
    atomicAdd(dst + 1, r.y);
    atomicAdd(dst + 2, r.z);
    atomicAdd(dst + 3, r.w);
#endif
    if (l == 0) atomicAdd(&sal[o * 2 + 0], alpha);
    if (l == 16) atomicAdd(&sal[o * 2 + 1], alpha);
}

// out = l2norm_per_head(leaky(0.5*(accA + salA*vA) + 0.5*(accB + salB*vB)))
__global__ void combine(const float* __restrict__ accA, const float* __restrict__ salA,
                        const float* __restrict__ vA,
                        const float* __restrict__ accB, const float* __restrict__ salB,
                        const float* __restrict__ vB,
                        float* __restrict__ out)
{
    int i = blockIdx.x, j = threadIdx.x;
    int h = j >> 6;
    float a = accA[i * 128 + j] + salA[i * 2 + h] * vA[i * 128 + j];
    float b = accB[i * 128 + j] + salB[i * 2 + h] * vB[i * 128 + j];
    float v = 0.5f * (a + b);
    v = (v > 0.f) ? v : kNEG * v;
    float s = wsum(v * v);
    __shared__ float sm[4];
    if ((j & 31) == 0) sm[j >> 5] = s;
    __syncthreads();
    float tot = sm[h * 2] + sm[h * 2 + 1];
    out[i * 128 + j] = v / fmaxf(sqrtf(tot), kEPS);
}

// h_prime = l2norm_128(ent broadcast over heads + h)
__global__ void final_k(const float* __restrict__ ent, const float* __restrict__ h,
                        float* __restrict__ out)
{
    int i = blockIdx.x, j = threadIdx.x;
    float v = ent[i * 64 + (j & 63)] + h[i * 128 + j];
    float s = wsum(v * v);
    __shared__ float sm[4];
    if ((j & 31) == 0) sm[j >> 5] = s;
    __syncthreads();
    float tot = sm[0] + sm[1] + sm[2] + sm[3];
    out[i * 128 + j] = v / fmaxf(sqrtf(tot), kEPS);
}

// ------------------------- host orchestration -------------------------
namespace {
struct Ptrs {
    float *xn, *uA, *vA, *uB, *vB, *accA, *accB, *salA, *salB, *h, *ent, *wA, *wB;
    float *auA, *avA, *auB, *avB, *awA, *awB, *ebuf, *denom;
};

static void get_ptrs(Ptrs& p) {
    cudaGetSymbolAddress((void**)&p.xn, d_xn);
    cudaGetSymbolAddress((void**)&p.uA, d_uA);
    cudaGetSymbolAddress((void**)&p.vA, d_vA);
    cudaGetSymbolAddress((void**)&p.uB, d_uB);
    cudaGetSymbolAddress((void**)&p.vB, d_vB);
    cudaGetSymbolAddress((void**)&p.accA, d_accA);
    cudaGetSymbolAddress((void**)&p.accB, d_accB);
    cudaGetSymbolAddress((void**)&p.salA, d_salA);
    cudaGetSymbolAddress((void**)&p.salB, d_salB);
    cudaGetSymbolAddress((void**)&p.h, d_h);
    cudaGetSymbolAddress((void**)&p.ent, d_ent);
    cudaGetSymbolAddress((void**)&p.wA, d_wA);
    cudaGetSymbolAddress((void**)&p.wB, d_wB);
    cudaGetSymbolAddress((void**)&p.auA, d_auA);
    cudaGetSymbolAddress((void**)&p.avA, d_avA);
    cudaGetSymbolAddress((void**)&p.auB, d_auB);
    cudaGetSymbolAddress((void**)&p.avB, d_avB);
    cudaGetSymbolAddress((void**)&p.awA, d_awA);
    cudaGetSymbolAddress((void**)&p.awB, d_awB);
    cudaGetSymbolAddress((void**)&p.ebuf, d_ebuf);
    cudaGetSymbolAddress((void**)&p.denom, d_denom);
}

static void run_layer(const Ptrs& p,
                      const float* A, int lda, int K, int ldw,
                      const float* Wi, const float* bi, const float* ai,
                      const float* Wo, const float* bo, const float* ao,
                      const float* g,
                      const int* rowp, const int* colp, const int* et,
                      float* outH)
{
    // fused node projections: uA,vA,uB,vB in one launch
    dim3 gg((NN + 127) / 128, 4);
    gemm4<<<gg, 256>>>(A, lda, K, Wi, Wo, ldw, p.uA, p.vA, p.uB, p.vB, NN);
    // relation projections (bias folded here)
    relproj<<<(RR * 128 + 255) / 256, 256>>>(g, GS, Wi, ldw, 2 * K, bi, p.wA, RR, 128);
    relproj<<<(RR * 128 + 255) / 256, 256>>>(g, GS, Wo, ldw, 2 * K, bo, p.wB, RR, 128);
    // attention scalar precomputes
    attdot<<<(NN + 7) / 8, 256>>>(p.uA, ai, p.auA, NN);
    attdot<<<(NN + 7) / 8, 256>>>(p.vA, ai, p.avA, NN);
    attdot<<<(NN + 7) / 8, 256>>>(p.uB, ao, p.auB, NN);
    attdot<<<(NN + 7) / 8, 256>>>(p.vB, ao, p.avB, NN);
    attdot<<<(RR + 7) / 8, 256>>>(p.wA, ai, p.awA, RR);
    attdot<<<(RR + 7) / 8, 256>>>(p.wB, ao, p.awB, RR);
    // accumulators
    zero_f<<<(NN * 128 + 255) / 256, 256>>>(p.accA, NN * 128);
    zero_f<<<(NN * 128 + 255) / 256, 256>>>(p.accB, NN * 128);
    zero_f<<<(NN * 2 + 255) / 256, 256>>>(p.salA, NN * 2);
    zero_f<<<(NN * 2 + 255) / 256, 256>>>(p.salB, NN * 2);
    // "in": seg=row, scatter to col
    zero_f<<<(NN * 2 + 255) / 256, 256>>>(p.denom, NN * 2);
    pass_a<<<(EE + 255) / 256, 256>>>(rowp, colp, et, p.auA, p.avA, p.awA, p.ebuf, p.denom);
    pass_b<<<(EE + 7) / 8, 256>>>(rowp, colp, et, p.uA, p.wA, p.ebuf, p.denom, p.accA, p.salA);
    // "out": seg=col, scatter to row
    zero_f<<<(NN * 2 + 255) / 256, 256>>>(p.denom, NN * 2);
    pass_a<<<(EE + 255) / 256, 256>>>(colp, rowp, et, p.auB, p.avB, p.awB, p.ebuf, p.denom);
    pass_b<<<(EE + 7) / 8, 256>>>(colp, rowp, et, p.uB, p.wB, p.ebuf, p.denom, p.accB, p.salB);
    combine<<<NN, 128>>>(p.accA, p.salA, p.vA, p.accB, p.salB, p.vB, outH);
}
}  // namespace

extern "C" void kernel_launch(void* const* d_in, const int* in_sizes, int n_in,
                              void* d_out, int out_size)
{
    const float* x   = (const float*)d_in[0];
    const float* g   = (const float*)d_in[1];
    const int*   ei  = (const int*)d_in[2];
    const int*   et  = (const int*)d_in[3];
    const float* W1i = (const float*)d_in[4];
    const float* b1i = (const float*)d_in[5];
    const float* a1i = (const float*)d_in[6];
    const float* W1o = (const float*)d_in[7];
    const float* b1o = (const float*)d_in[8];
    const float* a1o = (const float*)d_in[9];
    const float* W2i = (const float*)d_in[10];
    const float* b2i = (const float*)d_in[11];
    const float* a2i = (const float*)d_in[12];
    const float* W2o = (const float*)d_in[13];
    const float* b2o = (const float*)d_in[14];
    const float* a2o = (const float*)d_in[15];
    const float* We  = (const float*)d_in[16];
    const float* be  = (const float*)d_in[17];
    const float* Wr  = (const float*)d_in[18];
    const float* br  = (const float*)d_in[19];
    float* out = (float*)d_out;

    const int* rowp = ei;
    const int* colp = ei + EE;

    Ptrs p;
    get_ptrs(p);

    // x normalize
    norm_x<<<NN, 128>>>(x, p.xn);

    // layer 1: input xn [NN,100], d1 = 300
    run_layer(p, p.xn, XS, XS, 2 * XS + GS,
              W1i, b1i, a1i, W1o, b1o, a1o, g, rowp, colp, et, p.h);

    // layer 2: input h [NN,128], d2 = 356
    run_layer(p, p.h, 128, 128, 2 * 128 + GS,
              W2i, b2i, a2i, W2o, b2o, a2o, g, rowp, colp, et, p.h);

    // entity layer: ent = xn @ We.T + be  [NN,64]
    dim3 ge((NN + 63) / 64, 1);
    gemm_wt<<<ge, 256>>>(p.xn, XS, We, XS, XS, be, p.ent, 64, NN);

    // h_prime (l2norm over 128) -> out[0 : NN*128)
    final_k<<<NN, 128>>>(p.ent, p.h, out);

    // g_prime = g @ Wr.T + br -> out[NN*128 : NN*128 + RR*128)
    relproj<<<(RR * 128 + 255) / 256, 256>>>(g, GS, Wr, GS, 0, br, out + NN * 128, RR, 128);
}

// round 3
// speedup vs baseline: 1.9501x; 1.1141x over previous
#include <cuda_runtime.h>
#include <math.h>

#define NN 50000
#define EE 400000
#define RR 500
#define XS 100
#define GS 100

static __device__ __constant__ float kNEG = 0.01f;
static __device__ __constant__ float kEPS = 1e-12f;

// ------------------------- scratch (device globals) -------------------------
__device__ float d_xn[NN * XS];
__device__ float d_uA[NN * 128];
__device__ float d_vA[NN * 128];
__device__ float d_uB[NN * 128];
__device__ float d_vB[NN * 128];
__device__ float d_accA[NN * 128];
__device__ float d_accB[NN * 128];
__device__ float d_salA[NN * 2];
__device__ float d_salB[NN * 2];
__device__ float d_h[NN * 128];
__device__ float d_ent[NN * 64];
__device__ float d_wA[RR * 128];
__device__ float d_wB[RR * 128];
__device__ float d_auA[NN * 2];
__device__ float d_avA[NN * 2];
__device__ float d_auB[NN * 2];
__device__ float d_avB[NN * 2];
__device__ float d_awA[RR * 2];
__device__ float d_awB[RR * 2];
__device__ float d_ebA[EE * 2];
__device__ float d_ebB[EE * 2];
__device__ float d_denA[NN * 2];
__device__ float d_denB[NN * 2];
__device__ float d_q[8 * 128];

// ------------------------- helpers -------------------------
__device__ __forceinline__ float wsum(float v) {
#pragma unroll
    for (int o = 16; o > 0; o >>= 1) v += __shfl_xor_sync(0xffffffffu, v, o);
    return v;
}

// L2-normalize rows of x [NN, XS]; blockDim = 128, one block per row
__global__ void norm_x(const float* __restrict__ x, float* __restrict__ xn) {
    int i = blockIdx.x;
    int j = threadIdx.x;
    float v = (j < XS) ? x[i * XS + j] : 0.f;
    float s = wsum(v * v);
    __shared__ float sm[4];
    if ((j & 31) == 0) sm[j >> 5] = s;
    __syncthreads();
    float tot = sm[0] + sm[1] + sm[2] + sm[3];
    if (j < XS) xn[i * XS + j] = v / fmaxf(sqrtf(tot), kEPS);
}

// Fused 4-projection GEMM: y=0..3 computes C_y[M x 128] = A @ Wsel[:, koff:koff+K].T
__global__ __launch_bounds__(256) void gemm4(
    const float* __restrict__ A, int lda, int K,
    const float* __restrict__ Wi, const float* __restrict__ Wo, int ldw,
    float* __restrict__ uA, float* __restrict__ vA,
    float* __restrict__ uB, float* __restrict__ vB, int M)
{
    int y = blockIdx.y;
    const float* W = (y < 2) ? Wi : Wo;
    int koff = (y & 1) ? K : 0;
    float* C = (y == 0) ? uA : (y == 1) ? vA : (y == 2) ? uB : vB;

    __shared__ float As[16][132];   // [k][m]
    __shared__ float Bs[16][132];   // [k][n]
    int m0 = blockIdx.x * 128;
    int tx = threadIdx.x & 15;      // n: tx*8
    int ty = threadIdx.x >> 4;      // m: ty*8
    float acc[8][8] = {};

    for (int k0 = 0; k0 < K; k0 += 16) {
        {
            int m = threadIdx.x >> 1;
            int kb = (threadIdx.x & 1) * 8;
            int gm = m0 + m;
#pragma unroll
            for (int i = 0; i < 8; i++) {
                int gk = k0 + kb + i;
                As[kb + i][m] = (gm < M && gk < K) ? A[gm * lda + gk] : 0.f;
            }
        }
        {
            int n = threadIdx.x >> 1;
            int kb = (threadIdx.x & 1) * 8;
#pragma unroll
            for (int i = 0; i < 8; i++) {
                int gk = k0 + kb + i;
                Bs[kb + i][n] = (gk < K) ? W[n * ldw + koff + gk] : 0.f;
            }
        }
        __syncthreads();
#pragma unroll
        for (int k = 0; k < 16; k++) {
            float4 a0 = *(const float4*)&As[k][ty * 8];
            float4 a1 = *(const float4*)&As[k][ty * 8 + 4];
            float4 b0 = *(const float4*)&Bs[k][tx * 8];
            float4 b1 = *(const float4*)&Bs[k][tx * 8 + 4];
            float av[8] = {a0.x, a0.y, a0.z, a0.w, a1.x, a1.y, a1.z, a1.w};
            float bv[8] = {b0.x, b0.y, b0.z, b0.w, b1.x, b1.y, b1.z, b1.w};
#pragma unroll
            for (int i = 0; i < 8; i++)
#pragma unroll
                for (int j = 0; j < 8; j++)
                    acc[i][j] = fmaf(av[i], bv[j], acc[i][j]);
        }
        __syncthreads();
    }
#pragma unroll
    for (int i = 0; i < 8; i++) {
        int gm = m0 + ty * 8 + i;
        if (gm >= M) continue;
#pragma unroll
        for (int j = 0; j < 8; j += 4) {
            float4 v = make_float4(acc[i][j], acc[i][j + 1], acc[i][j + 2], acc[i][j + 3]);
            *(float4*)&C[gm * 128 + tx * 8 + j] = v;
        }
    }
}

// C[M x N] = A[M x K] @ W.T (+bias) — entity layer
__global__ __launch_bounds__(256) void gemm_wt(
    const float* __restrict__ A, int lda,
    const float* __restrict__ W, int ldw, int K,
    const float* __restrict__ bias,
    float* __restrict__ C, int ldc, int M)
{
    __shared__ float As[64][17];
    __shared__ float Bs[16][65];
    int m0 = blockIdx.x * 64, n0 = blockIdx.y * 64;
    int tx = threadIdx.x & 15, ty = threadIdx.x >> 4;
    float acc[4][4] = {};
    for (int k0 = 0; k0 < K; k0 += 16) {
#pragma unroll
        for (int i = 0; i < 4; i++) {
            int li = threadIdx.x + i * 256;
            int k = li & 15, m = li >> 4;
            int gm = m0 + m, gk = k0 + k;
            As[m][k] = (gm < M && gk < K) ? A[gm * lda + gk] : 0.f;
        }
#pragma unroll
        for (int i = 0; i < 4; i++) {
            int li = threadIdx.x + i * 256;
            int k = li & 15, n = li >> 4;
            int gk = k0 + k;
            Bs[k][n] = (gk < K) ? W[(n0 + n) * ldw + gk] : 0.f;
        }
        __syncthreads();
#pragma unroll
        for (int k = 0; k < 16; k++) {
            float a[4], b[4];
#pragma unroll
            for (int i = 0; i < 4; i++) a[i] = As[ty * 4 + i][k];
#pragma unroll
            for (int j = 0; j < 4; j++) b[j] = Bs[k][tx * 4 + j];
#pragma unroll
            for (int i = 0; i < 4; i++)
#pragma unroll
                for (int j = 0; j < 4; j++)
                    acc[i][j] = fmaf(a[i], b[j], acc[i][j]);
        }
        __syncthreads();
    }
#pragma unroll
    for (int i = 0; i < 4; i++) {
        int gm = m0 + ty * 4 + i;
        if (gm >= M) continue;
#pragma unroll
        for (int j = 0; j < 4; j++) {
            int gn = n0 + tx * 4 + j;
            C[gm * ldc + gn] = acc[i][j] + bias[gn];
        }
    }
}

// q[y][k] = sum_c att[h*64+c] * W[h*64+c, koff+k]; y = dir*4 + sel*2 + h
__global__ void qprep(const float* __restrict__ Wi, const float* __restrict__ Wo,
                      int ldw, int K,
                      const float* __restrict__ ai, const float* __restrict__ ao,
                      float* __restrict__ q)
{
    int y = blockIdx.x, k = threadIdx.x;
    const float* W = (y < 4) ? Wi : Wo;
    const float* att = (y < 4) ? ai : ao;
    int sel = (y >> 1) & 1, h = y & 1;
    int koff = sel * K;
    float s = 0.f;
    if (k < K)
        for (int c = 0; c < 64; c++)
            s = fmaf(att[h * 64 + c], W[(h * 64 + c) * ldw + koff + k], s);
    q[y * 128 + k] = (k < K) ? s : 0.f;
}

// One pass over A computing au/av for both directions. Warp per node.
__global__ __launch_bounds__(256) void auav(
    const float* __restrict__ A, int lda, int K, const float* __restrict__ q,
    float* __restrict__ auA, float* __restrict__ avA,
    float* __restrict__ auB, float* __restrict__ avB, int M)
{
    int m = blockIdx.x * 8 + (threadIdx.x >> 5);
    if (m >= M) return;
    int l = threadIdx.x & 31;
    float s[8] = {};
    for (int k = l; k < K; k += 32) {
        float a = A[m * lda + k];
#pragma unroll
        for (int y = 0; y < 8; y++) s[y] = fmaf(a, q[y * 128 + k], s[y]);
    }
#pragma unroll
    for (int y = 0; y < 8; y++) {
#pragma unroll
        for (int o = 16; o > 0; o >>= 1) s[y] += __shfl_xor_sync(0xffffffffu, s[y], o);
    }
    if (l == 0) {
        auA[m * 2 + 0] = s[0]; auA[m * 2 + 1] = s[1];
        avA[m * 2 + 0] = s[2]; avA[m * 2 + 1] = s[3];
        auB[m * 2 + 0] = s[4]; auB[m * 2 + 1] = s[5];
        avB[m * 2 + 0] = s[6]; avB[m * 2 + 1] = s[7];
    }
}

// Relation projection for both directions + fused aw reduction.
// grid (RR, 2), block 128. y=0 -> (Wi, bi, ai, wA, awA), y=1 -> Wo set.
__global__ void relproj2(const float* __restrict__ g,
                         const float* __restrict__ Wi, const float* __restrict__ bi,
                         const float* __restrict__ ai,
                         const float* __restrict__ Wo, const float* __restrict__ bo,
                         const float* __restrict__ ao,
                         int ldw, int koff,
                         float* __restrict__ wA, float* __restrict__ wB,
                         float* __restrict__ awA, float* __restrict__ awB)
{
    int r = blockIdx.x, y = blockIdx.y;
    const float* W = y ? Wo : Wi;
    const float* b = y ? bo : bi;
    const float* att = y ? ao : ai;
    float* wout = y ? wB : wA;
    float* awout = y ? awB : awA;
    __shared__ float gs[GS];
    int n = threadIdx.x;
    if (n < GS) gs[n] = g[r * GS + n];
    __syncthreads();
    float acc = b[n];
    const float* wr = W + n * ldw + koff;
#pragma unroll 4
    for (int k = 0; k < GS; k++) acc = fmaf(wr[k], gs[k], acc);
    wout[r * 128 + n] = acc;
    float s = wsum(acc * att[n]);
    __shared__ float sm[4];
    if ((n & 31) == 0) sm[n >> 5] = s;
    __syncthreads();
    if (n == 0) awout[r * 2 + 0] = sm[0] + sm[1];
    if (n == 64) awout[r * 2 + 1] = sm[2] + sm[3];
}

// g_prime: block per relation
__global__ void relproj_out(const float* __restrict__ g, const float* __restrict__ Wr,
                            const float* __restrict__ br, float* __restrict__ out)
{
    int r = blockIdx.x;
    __shared__ float gs[GS];
    int n = threadIdx.x;
    if (n < GS) gs[n] = g[r * GS + n];
    __syncthreads();
    float acc = br[n];
    const float* wr = Wr + n * GS;
#pragma unroll 4
    for (int k = 0; k < GS; k++) acc = fmaf(wr[k], gs[k], acc);
    out[r * 128 + n] = acc;
}

// Fused pass A for both directions: one thread per edge.
__global__ __launch_bounds__(256) void pass_a2(
    const int* __restrict__ rowp, const int* __restrict__ colp, const int* __restrict__ et,
    const float* __restrict__ auA, const float* __restrict__ avA, const float* __restrict__ awA,
    const float* __restrict__ auB, const float* __restrict__ avB, const float* __restrict__ awB,
    float* __restrict__ ebA, float* __restrict__ ebB,
    float* __restrict__ denA, float* __restrict__ denB)
{
    int e = blockIdx.x * blockDim.x + threadIdx.x;
    if (e >= EE) return;
    int r = rowp[e], c = colp[e], t = et[e];
#pragma unroll
    for (int h = 0; h < 2; h++) {
        float a = auA[r * 2 + h] + avA[c * 2 + h] + awA[t * 2 + h];
        a = (a > 0.f) ? a : kNEG * a;
        float ex = expf(a);
        ebA[e * 2 + h] = ex;
        atomicAdd(&denA[r * 2 + h], ex);
        float b = auB[c * 2 + h] + avB[r * 2 + h] + awB[t * 2 + h];
        b = (b > 0.f) ? b : kNEG * b;
        float exb = expf(b);
        ebB[e * 2 + h] = exb;
        atomicAdd(&denB[c * 2 + h], exb);
    }
}

// Fused pass B for both directions: warp per edge.
__global__ __launch_bounds__(256) void pass_b2(
    const int* __restrict__ rowp, const int* __restrict__ colp, const int* __restrict__ et,
    const float* __restrict__ uA, const float* __restrict__ wA,
    const float* __restrict__ uB, const float* __restrict__ wB,
    const float* __restrict__ ebA, const float* __restrict__ denA,
    const float* __restrict__ ebB, const float* __restrict__ denB,
    float* __restrict__ accA, float* __restrict__ salA,
    float* __restrict__ accB, float* __restrict__ salB)
{
    int e = blockIdx.x * 8 + (threadIdx.x >> 5);
    if (e >= EE) return;
    int l = threadIdx.x & 31;
    int r = rowp[e], c = colp[e], t = et[e];
    int h = l >> 4;
    float aA = ebA[e * 2 + h] / denA[r * 2 + h];
    float aB = ebB[e * 2 + h] / denB[c * 2 + h];

    // direction A: seg=row(r), scatter to col(c)
    {
        float4 uv = ((const float4*)(uA + (size_t)r * 128))[l];
        float4 wv = ((const float4*)(wA + (size_t)t * 128))[l];
        float4 o;
        o.x = aA * (uv.x + wv.x); o.y = aA * (uv.y + wv.y);
        o.z = aA * (uv.z + wv.z); o.w = aA * (uv.w + wv.w);
        float* dst = accA + (size_t)c * 128 + l * 4;
        asm volatile("red.global.add.v4.f32 [%0], {%1, %2, %3, %4};"
                     :: "l"(dst), "f"(o.x), "f"(o.y), "f"(o.z), "f"(o.w) : "memory");
    }
    // direction B: seg=col(c), scatter to row(r)
    {
        float4 uv = ((const float4*)(uB + (size_t)c * 128))[l];
        float4 wv = ((const float4*)(wB + (size_t)t * 128))[l];
        float4 o;
        o.x = aB * (uv.x + wv.x); o.y = aB * (uv.y + wv.y);
        o.z = aB * (uv.z + wv.z); o.w = aB * (uv.w + wv.w);
        float* dst = accB + (size_t)r * 128 + l * 4;
        asm volatile("red.global.add.v4.f32 [%0], {%1, %2, %3, %4};"
                     :: "l"(dst), "f"(o.x), "f"(o.y), "f"(o.z), "f"(o.w) : "memory");
    }
    if (l == 0)  { atomicAdd(&salA[c * 2 + 0], aA); atomicAdd(&salB[r * 2 + 0], aB); }
    if (l == 16) { atomicAdd(&salA[c * 2 + 1], aA); atomicAdd(&salB[r * 2 + 1], aB); }
}

// out = l2norm_per_head(leaky(0.5*(accA + salA*vA) + 0.5*(accB + salB*vB)))
__global__ void combine(const float* __restrict__ accA, const float* __restrict__ salA,
                        const float* __restrict__ vA,
                        const float* __restrict__ accB, const float* __restrict__ salB,
                        const float* __restrict__ vB,
                        float* __restrict__ out)
{
    int i = blockIdx.x, j = threadIdx.x;
    int h = j >> 6;
    float a = accA[i * 128 + j] + salA[i * 2 + h] * vA[i * 128 + j];
    float b = accB[i * 128 + j] + salB[i * 2 + h] * vB[i * 128 + j];
    float v = 0.5f * (a + b);
    v = (v > 0.f) ? v : kNEG * v;
    float s = wsum(v * v);
    __shared__ float sm[4];
    if ((j & 31) == 0) sm[j >> 5] = s;
    __syncthreads();
    float tot = sm[h * 2] + sm[h * 2 + 1];
    out[i * 128 + j] = v / fmaxf(sqrtf(tot), kEPS);
}

// h_prime = l2norm_128(ent broadcast over heads + h)
__global__ void final_k(const float* __restrict__ ent, const float* __restrict__ h,
                        float* __restrict__ out)
{
    int i = blockIdx.x, j = threadIdx.x;
    float v = ent[i * 64 + (j & 63)] + h[i * 128 + j];
    float s = wsum(v * v);
    __shared__ float sm[4];
    if ((j & 31) == 0) sm[j >> 5] = s;
    __syncthreads();
    float tot = sm[0] + sm[1] + sm[2] + sm[3];
    out[i * 128 + j] = v / fmaxf(sqrtf(tot), kEPS);
}

// ------------------------- host orchestration -------------------------
namespace {
struct Ptrs {
    float *xn, *uA, *vA, *uB, *vB, *accA, *accB, *salA, *salB, *h, *ent, *wA, *wB;
    float *auA, *avA, *auB, *avB, *awA, *awB, *ebA, *ebB, *denA, *denB, *q;
};

static void get_ptrs(Ptrs& p) {
    cudaGetSymbolAddress((void**)&p.xn, d_xn);
    cudaGetSymbolAddress((void**)&p.uA, d_uA);
    cudaGetSymbolAddress((void**)&p.vA, d_vA);
    cudaGetSymbolAddress((void**)&p.uB, d_uB);
    cudaGetSymbolAddress((void**)&p.vB, d_vB);
    cudaGetSymbolAddress((void**)&p.accA, d_accA);
    cudaGetSymbolAddress((void**)&p.accB, d_accB);
    cudaGetSymbolAddress((void**)&p.salA, d_salA);
    cudaGetSymbolAddress((void**)&p.salB, d_salB);
    cudaGetSymbolAddress((void**)&p.h, d_h);
    cudaGetSymbolAddress((void**)&p.ent, d_ent);
    cudaGetSymbolAddress((void**)&p.wA, d_wA);
    cudaGetSymbolAddress((void**)&p.wB, d_wB);
    cudaGetSymbolAddress((void**)&p.auA, d_auA);
    cudaGetSymbolAddress((void**)&p.avA, d_avA);
    cudaGetSymbolAddress((void**)&p.auB, d_auB);
    cudaGetSymbolAddress((void**)&p.avB, d_avB);
    cudaGetSymbolAddress((void**)&p.awA, d_awA);
    cudaGetSymbolAddress((void**)&p.awB, d_awB);
    cudaGetSymbolAddress((void**)&p.ebA, d_ebA);
    cudaGetSymbolAddress((void**)&p.ebB, d_ebB);
    cudaGetSymbolAddress((void**)&p.denA, d_denA);
    cudaGetSymbolAddress((void**)&p.denB, d_denB);
    cudaGetSymbolAddress((void**)&p.q, d_q);
}

static void run_layer(const Ptrs& p,
                      const float* A, int lda, int K, int ldw,
                      const float* Wi, const float* bi, const float* ai,
                      const float* Wo, const float* bo, const float* ao,
                      const float* g,
                      const int* rowp, const int* colp, const int* et,
                      float* outH)
{
    // node projections (4 fused)
    dim3 gg((NN + 127) / 128, 4);
    gemm4<<<gg, 256>>>(A, lda, K, Wi, Wo, ldw, p.uA, p.vA, p.uB, p.vB, NN);
    // attention q-vectors + au/av in one pass over A
    qprep<<<8, 128>>>(Wi, Wo, ldw, K, ai, ao, p.q);
    auav<<<(NN + 7) / 8, 256>>>(A, lda, K, p.q, p.auA, p.avA, p.auB, p.avB, NN);
    // relation projections + aw (both directions, one launch)
    dim3 gr(RR, 2);
    relproj2<<<gr, 128>>>(g, Wi, bi, ai, Wo, bo, ao, ldw, 2 * K,
                          p.wA, p.wB, p.awA, p.awB);
    // zero accumulators
    cudaMemsetAsync(p.accA, 0, NN * 128 * sizeof(float));
    cudaMemsetAsync(p.accB, 0, NN * 128 * sizeof(float));
    cudaMemsetAsync(p.salA, 0, NN * 2 * sizeof(float));
    cudaMemsetAsync(p.salB, 0, NN * 2 * sizeof(float));
    cudaMemsetAsync(p.denA, 0, NN * 2 * sizeof(float));
    cudaMemsetAsync(p.denB, 0, NN * 2 * sizeof(float));
    // edge passes (both directions fused)
    pass_a2<<<(EE + 255) / 256, 256>>>(rowp, colp, et,
                                       p.auA, p.avA, p.awA, p.auB, p.avB, p.awB,
                                       p.ebA, p.ebB, p.denA, p.denB);
    pass_b2<<<(EE + 7) / 8, 256>>>(rowp, colp, et, p.uA, p.wA, p.uB, p.wB,
                                   p.ebA, p.denA, p.ebB, p.denB,
                                   p.accA, p.salA, p.accB, p.salB);
    combine<<<NN, 128>>>(p.accA, p.salA, p.vA, p.accB, p.salB, p.vB, outH);
}
}  // namespace

extern "C" void kernel_launch(void* const* d_in, const int* in_sizes, int n_in,
                              void* d_out, int out_size)
{
    const float* x   = (const float*)d_in[0];
    const float* g   = (const float*)d_in[1];
    const int*   ei  = (const int*)d_in[2];
    const int*   et  = (const int*)d_in[3];
    const float* W1i = (const float*)d_in[4];
    const float* b1i = (const float*)d_in[5];
    const float* a1i = (const float*)d_in[6];
    const float* W1o = (const float*)d_in[7];
    const float* b1o = (const float*)d_in[8];
    const float* a1o = (const float*)d_in[9];
    const float* W2i = (const float*)d_in[10];
    const float* b2i = (const float*)d_in[11];
    const float* a2i = (const float*)d_in[12];
    const float* W2o = (const float*)d_in[13];
    const float* b2o = (const float*)d_in[14];
    const float* a2o = (const float*)d_in[15];
    const float* We  = (const float*)d_in[16];
    const float* be  = (const float*)d_in[17];
    const float* Wr  = (const float*)d_in[18];
    const float* br  = (const float*)d_in[19];
    float* out = (float*)d_out;

    const int* rowp = ei;
    const int* colp = ei + EE;

    Ptrs p;
    get_ptrs(p);

    norm_x<<<NN, 128>>>(x, p.xn);

    // layer 1: input xn [NN,100], d1 = 300
    run_layer(p, p.xn, XS, XS, 2 * XS + GS,
              W1i, b1i, a1i, W1o, b1o, a1o, g, rowp, colp, et, p.h);

    // layer 2: input h [NN,128], d2 = 356
    run_layer(p, p.h, 128, 128, 2 * 128 + GS,
              W2i, b2i, a2i, W2o, b2o, a2o, g, rowp, colp, et, p.h);

    // entity layer: ent = xn @ We.T + be  [NN,64]
    dim3 ge((NN + 63) / 64, 1);
    gemm_wt<<<ge, 256>>>(p.xn, XS, We, XS, XS, be, p.ent, 64, NN);

    // h_prime -> out[0 : NN*128)
    final_k<<<NN, 128>>>(p.ent, p.h, out);

    // g_prime -> out[NN*128 : NN*128 + RR*128)
    relproj_out<<<RR, 128>>>(g, Wr, br, out + NN * 128);
}